// round 1
// baseline (speedup 1.0000x reference)
#include <cuda_runtime.h>
#include <math.h>

#define NN 8192
#define DD 64
#define EE 64
#define LEAK 0.7f

// scratch: transposed embeddings and transformed embeddings (k-major, [E][N])
__device__ float U_t[EE * NN];
__device__ float V_t[EE * NN];

// ---------------------------------------------------------------------------
// Prep: V = U @ W ; write U^T and V^T (k-major) for conflict-free smem tiling
// grid: 32 x 256 (one thread per row of U)
// ---------------------------------------------------------------------------
__global__ void __launch_bounds__(256) prep_kernel(const float* __restrict__ U,
                                                   const float* __restrict__ W) {
    __shared__ float Ws[EE * EE];
    int tid = threadIdx.x;
    for (int idx = tid; idx < EE * EE; idx += 256) Ws[idx] = W[idx];
    __syncthreads();

    int i = blockIdx.x * 256 + tid;  // row index, 0..8191

    float4 acc[EE / 4];
#pragma unroll
    for (int f = 0; f < EE / 4; f++) acc[f] = make_float4(0.f, 0.f, 0.f, 0.f);

    const float* urow = U + i * EE;
#pragma unroll 4
    for (int e = 0; e < EE; e++) {
        float u = urow[e];
        U_t[e * NN + i] = u;  // coalesced across threads
#pragma unroll
        for (int f = 0; f < EE / 4; f++) {
            float4 w = *(const float4*)&Ws[e * EE + f * 4];
            acc[f].x += u * w.x;
            acc[f].y += u * w.y;
            acc[f].z += u * w.z;
            acc[f].w += u * w.w;
        }
    }
#pragma unroll
    for (int f = 0; f < EE / 4; f++) {
        V_t[(f * 4 + 0) * NN + i] = acc[f].x;
        V_t[(f * 4 + 1) * NN + i] = acc[f].y;
        V_t[(f * 4 + 2) * NN + i] = acc[f].z;
        V_t[(f * 4 + 3) * NN + i] = acc[f].w;
    }
}

// ---------------------------------------------------------------------------
// Main fused kernel.
// Each block: j-tile of 64, loops over all i in chunks of 64.
// Phase A: scores S[i][j] = dot64(V[i], U[j]) -> T = sigmoid(+bias), mask diag
// Phase B: acc[b][j][d] += T[i][j] * (g[b][i] * states[b][i][d])
// Both batches share the score computation (T is batch-independent).
// smem: Ujt[64][64] + Vit[64][64] + Tt[64][64] + eff[2][64][64] = 80 KB
// ---------------------------------------------------------------------------
__global__ void __launch_bounds__(256) dyadic_kernel(const float* __restrict__ S,
                                                     const float* __restrict__ prof,
                                                     const float* __restrict__ bias_p,
                                                     float* __restrict__ out) {
    extern __shared__ float sm[];
    float* Ujt = sm;                 // [k][j], k-major, row stride 64
    float* Vit = sm + 4096;          // [k][i]
    float* Tt  = sm + 8192;          // [i][j]
    float* eff = sm + 12288;         // [b][i][d]
    float4* effv = (float4*)eff;

    const int tid = threadIdx.x;
    const int j0 = blockIdx.x * 64;
    const float bias = *bias_p;

    // phase-A thread ids: 4x4 micro-tile of the 64x64 score tile
    const int ti = tid >> 4;   // 0..15 -> i = ti*4 + a
    const int tj = tid & 15;   // 0..15 -> j = tj*4 + b
    // phase-B thread ids
    const int jj = tid & 63;   // j within tile
    const int dq = tid >> 6;   // d quarter (16 floats each)

    // load Ujt once (coalesced gmem, conflict-free smem)
    {
        const float4* Ut4 = (const float4*)U_t;
        float4* Ujt4 = (float4*)Ujt;
        for (int idx = tid; idx < 1024; idx += 256) {
            int k = idx >> 4, c = idx & 15;
            Ujt4[k * 16 + c] = Ut4[k * (NN / 4) + (j0 >> 2) + c];
        }
    }

    float4 acc0[4], acc1[4];
#pragma unroll
    for (int dd = 0; dd < 4; dd++) {
        acc0[dd] = make_float4(0.f, 0.f, 0.f, 0.f);
        acc1[dd] = make_float4(0.f, 0.f, 0.f, 0.f);
    }

    __syncthreads();

    for (int i0 = 0; i0 < NN; i0 += 64) {
        // ---- stage V^T tile and gated-source tile ----
        {
            const float4* Vt4 = (const float4*)V_t;
            float4* Vit4 = (float4*)Vit;
            for (int idx = tid; idx < 1024; idx += 256) {
                int k = idx >> 4, c = idx & 15;
                Vit4[k * 16 + c] = Vt4[k * (NN / 4) + (i0 >> 2) + c];
            }
            const float4* S4 = (const float4*)S;
            for (int idx = tid; idx < 2048; idx += 256) {
                int b = idx >> 10;
                int rem = idx & 1023;
                int r = rem >> 4;   // i within chunk
                int c = rem & 15;   // float4 column
                float g = prof[b * NN + i0 + r] - LEAK;
                g = g > 0.f ? g : 0.f;
                float4 v = S4[(b * NN + i0 + r) * 16 + c];
                effv[idx] = make_float4(v.x * g, v.y * g, v.z * g, v.w * g);
            }
        }
        __syncthreads();

        // ---- phase A: 64x64 score tile, 4x4 per thread ----
        {
            float s[4][4];
#pragma unroll
            for (int a = 0; a < 4; a++)
#pragma unroll
                for (int b = 0; b < 4; b++) s[a][b] = 0.f;

#pragma unroll 8
            for (int k = 0; k < 64; k++) {
                float4 va = *(const float4*)&Vit[k * 64 + ti * 4];
                float4 ub = *(const float4*)&Ujt[k * 64 + tj * 4];
                float av[4] = {va.x, va.y, va.z, va.w};
                float bv[4] = {ub.x, ub.y, ub.z, ub.w};
#pragma unroll
                for (int a = 0; a < 4; a++)
#pragma unroll
                    for (int b = 0; b < 4; b++) s[a][b] += av[a] * bv[b];
            }
#pragma unroll
            for (int a = 0; a < 4; a++) {
#pragma unroll
                for (int b = 0; b < 4; b++) {
                    int gi = i0 + ti * 4 + a;
                    int gj = j0 + tj * 4 + b;
                    float x = s[a][b] + bias;
                    float t = 1.f / (1.f + __expf(-x));
                    if (gi == gj) t = 0.f;
                    Tt[(ti * 4 + a) * 64 + (tj * 4 + b)] = t;
                }
            }
        }
        __syncthreads();

        // ---- phase B: accumulate leaked state ----
#pragma unroll 8
        for (int i = 0; i < 64; i++) {
            float t = Tt[i * 64 + jj];
            const float4* e0 = effv + (i * 16 + dq * 4);
            const float4* e1 = effv + (1024 + i * 16 + dq * 4);
#pragma unroll
            for (int dd = 0; dd < 4; dd++) {
                float4 v0 = e0[dd];
                acc0[dd].x += t * v0.x;
                acc0[dd].y += t * v0.y;
                acc0[dd].z += t * v0.z;
                acc0[dd].w += t * v0.w;
                float4 v1 = e1[dd];
                acc1[dd].x += t * v1.x;
                acc1[dd].y += t * v1.y;
                acc1[dd].z += t * v1.z;
                acc1[dd].w += t * v1.w;
            }
        }
        __syncthreads();
    }

    // ---- epilogue: out = states + leaked ----
    {
        const float4* S4 = (const float4*)S;
        float4* O4 = (float4*)out;
#pragma unroll
        for (int dd = 0; dd < 4; dd++) {
            int idx0 = (0 * NN + j0 + jj) * 16 + dq * 4 + dd;
            float4 sv = S4[idx0];
            O4[idx0] = make_float4(sv.x + acc0[dd].x, sv.y + acc0[dd].y,
                                   sv.z + acc0[dd].z, sv.w + acc0[dd].w);
            int idx1 = (1 * NN + j0 + jj) * 16 + dq * 4 + dd;
            float4 sv1 = S4[idx1];
            O4[idx1] = make_float4(sv1.x + acc1[dd].x, sv1.y + acc1[dd].y,
                                   sv1.z + acc1[dd].z, sv1.w + acc1[dd].w);
        }
    }
}

extern "C" void kernel_launch(void* const* d_in, const int* in_sizes, int n_in,
                              void* d_out, int out_size) {
    const float* S    = (const float*)d_in[0];  // task_states   [2,8192,64]
    const float* prof = (const float*)d_in[1];  // proficiency   [2,8192]
    const float* U    = (const float*)d_in[2];  // task_embeddings [8192,64]
    const float* W    = (const float*)d_in[3];  // bilinear_weight [1,64,64]
    const float* bias = (const float*)d_in[4];  // bilinear_bias  [1]
    float* out = (float*)d_out;

    prep_kernel<<<NN / 256, 256>>>(U, W);

    cudaFuncSetAttribute(dyadic_kernel,
                         cudaFuncAttributeMaxDynamicSharedMemorySize, 81920);
    dyadic_kernel<<<NN / 64, 256, 81920>>>(S, prof, bias, out);
}

// round 3
// speedup vs baseline: 3.5936x; 3.5936x over previous
#include <cuda_runtime.h>
#include <cuda_bf16.h>
#include <cstdint>

#define NN 8192
#define LEAK 0.7f

// ---------------- global scratch (plain row-major bf16 hi/lo splits) ------
__device__ __nv_bfloat16 gUh[NN * 64], gUl[NN * 64];   // U[row][k]
__device__ __nv_bfloat16 gVh[NN * 64], gVl[NN * 64];   // V[row][k]
__device__ __nv_bfloat16 gEh[64 * 128 * 128], gEl[64 * 128 * 128]; // [chunk][dcat][il]

// ---------------- helpers ----------------
__device__ __forceinline__ uint32_t smem_u32(const void* p) {
    uint32_t a;
    asm("{ .reg .u64 t; cvta.to.shared.u64 t, %1; cvt.u32.u64 %0, t; }" : "=r"(a) : "l"(p));
    return a;
}
#define LDSM4(R0, R1, R2, R3, A)                                              \
    asm volatile("ldmatrix.sync.aligned.m8n8.x4.shared.b16 {%0,%1,%2,%3}, [%4];" \
                 : "=r"(R0), "=r"(R1), "=r"(R2), "=r"(R3) : "r"(A))
#define MMA_BF16(c, a0, a1, a2, a3, b0, b1)                                   \
    asm volatile("mma.sync.aligned.m16n8k16.row.col.f32.bf16.bf16.f32 "       \
                 "{%0,%1,%2,%3},{%4,%5,%6,%7},{%8,%9},{%0,%1,%2,%3};"         \
                 : "+f"((c)[0]), "+f"((c)[1]), "+f"((c)[2]), "+f"((c)[3])     \
                 : "r"(a0), "r"(a1), "r"(a2), "r"(a3), "r"(b0), "r"(b1))

__device__ __forceinline__ void split2(float x, __nv_bfloat16& h, __nv_bfloat16& l) {
    h = __float2bfloat16(x);
    l = __float2bfloat16(x - __bfloat162float(h));
}

// ---------------- prep 1: V = U @ W; emit U,V hi/lo ----------------
__global__ void __launch_bounds__(256) prep_embed(const float* __restrict__ U,
                                                  const float* __restrict__ W) {
    __shared__ float Ws[64 * 64];
    int tid = threadIdx.x;
    for (int i = tid; i < 4096; i += 256) Ws[i] = W[i];
    __syncthreads();
    int w = tid >> 5, l = tid & 31;
    for (int r = 0; r < 8; r++) {
        int row = blockIdx.x * 64 + w * 8 + r;
        float u0 = U[row * 64 + l];
        float u1 = U[row * 64 + 32 + l];
        float v0 = 0.f, v1 = 0.f;
#pragma unroll
        for (int e = 0; e < 32; e++) {
            float ue = __shfl_sync(0xffffffffu, u0, e);
            v0 += ue * Ws[e * 64 + l];
            v1 += ue * Ws[e * 64 + 32 + l];
        }
#pragma unroll
        for (int e = 0; e < 32; e++) {
            float ue = __shfl_sync(0xffffffffu, u1, e);
            v0 += ue * Ws[(32 + e) * 64 + l];
            v1 += ue * Ws[(32 + e) * 64 + 32 + l];
        }
        __nv_bfloat16 h, lo;
        split2(u0, h, lo); gUh[row * 64 + l] = h;      gUl[row * 64 + l] = lo;
        split2(u1, h, lo); gUh[row * 64 + 32 + l] = h; gUl[row * 64 + 32 + l] = lo;
        split2(v0, h, lo); gVh[row * 64 + l] = h;      gVl[row * 64 + l] = lo;
        split2(v1, h, lo); gVh[row * 64 + 32 + l] = h; gVl[row * 64 + 32 + l] = lo;
    }
}

// ---------------- prep 2: eff[chunk][dcat][il] hi/lo (transposed) ----------
__global__ void __launch_bounds__(256) prep_eff(const float* __restrict__ S,
                                                const float* __restrict__ prof) {
    extern __shared__ float es[];  // [128 il][129] (dc)
    __shared__ float gg[256];
    int bx = blockIdx.x, tid = threadIdx.x;
    {
        int b = tid >> 7, il = tid & 127;
        float g = prof[b * NN + bx * 128 + il] - LEAK;
        gg[tid] = g > 0.f ? g : 0.f;
    }
    __syncthreads();
    for (int idx = tid; idx < 16384; idx += 256) {
        int il = idx >> 7, dc = idx & 127;
        int b = dc >> 6, d = dc & 63;
        es[il * 129 + dc] = S[(b * NN + bx * 128 + il) * 64 + d] * gg[b * 128 + il];
    }
    __syncthreads();
    int base = bx * 16384;
    for (int idx = tid; idx < 16384; idx += 256) {
        int dc = idx >> 7, il = idx & 127;
        float x = es[il * 129 + dc];
        __nv_bfloat16 h, lo;
        split2(x, h, lo);
        gEh[base + dc * 128 + il] = h;
        gEl[base + dc * 128 + il] = lo;
    }
}

// ---------------- main fused mma.sync kernel ----------------
// smem byte offsets (144 = 72 bf16 padded row; 272 = 136 bf16 padded row)
#define SM_UH 0u
#define SM_UL 9216u
#define SM_VH 18432u
#define SM_VL 36864u
#define SM_EH 55296u
#define SM_EL 90112u
#define SM_PTH 124928u
#define SM_PTL 142336u
#define SM_TOTAL 159744u

__global__ void __launch_bounds__(256, 1) dyadic_mma(const float* __restrict__ S,
                                                     const float* __restrict__ bias_p,
                                                     float* __restrict__ out) {
    extern __shared__ char sm[];
    const uint32_t sb = smem_u32(sm);
    const int tid = threadIdx.x, w = tid >> 5, lane = tid & 31;
    const int jc = blockIdx.x;
    const float bias = bias_p[0];

    // resident U tile (64 rows x 64 k, hi/lo), padded rows
    {
        const uint4* sh = (const uint4*)gUh + jc * 512;
        const uint4* sl = (const uint4*)gUl + jc * 512;
        for (int idx = tid; idx < 512; idx += 256) {
            int r = idx >> 3, c = idx & 7;
            *(uint4*)(sm + SM_UH + r * 144 + c * 16) = sh[idx];
            *(uint4*)(sm + SM_UL + r * 144 + c * 16) = sl[idx];
        }
    }

    // common ldmatrix lane-address components
    const int a_r = lane & 15;                       // A row within 16
    const int a_c = (lane & 16) ? 8 : 0;             // A col half
    const int b_r = (lane & 7) + ((lane & 16) ? 8 : 0);  // B row within 16 (2 n-blocks)
    const int b_c = (lane & 8) ? 8 : 0;              // B col half

    float d2[8][4];
#pragma unroll
    for (int nb = 0; nb < 8; nb++)
#pragma unroll
        for (int q = 0; q < 4; q++) d2[nb][q] = 0.f;

    const int mw = w & 3, nw = w >> 2;  // GEMM2 partition

    for (int t = 0; t < 64; t++) {
        __syncthreads();  // prev GEMM2 done reading E/PT; V/E free
        // ---- stage V (128x64) and E (128x128), hi/lo ----
        {
            const uint4* vh = (const uint4*)gVh + t * 1024;
            const uint4* vl = (const uint4*)gVl + t * 1024;
            for (int idx = tid; idx < 1024; idx += 256) {
                int r = idx >> 3, c = idx & 7;
                *(uint4*)(sm + SM_VH + r * 144 + c * 16) = vh[idx];
                *(uint4*)(sm + SM_VL + r * 144 + c * 16) = vl[idx];
            }
            const uint4* eh = (const uint4*)gEh + t * 2048;
            const uint4* el = (const uint4*)gEl + t * 2048;
            for (int idx = tid; idx < 2048; idx += 256) {
                int r = idx >> 4, c = idx & 15;
                *(uint4*)(sm + SM_EH + r * 272 + c * 16) = eh[idx];
                *(uint4*)(sm + SM_EL + r * 272 + c * 16) = el[idx];
            }
        }
        __syncthreads();

        // ---- GEMM1: C1[16i x 64j] per warp, K=64, 3-pass ----
        float c1[8][4];
#pragma unroll
        for (int nb = 0; nb < 8; nb++)
#pragma unroll
            for (int q = 0; q < 4; q++) c1[nb][q] = 0.f;

        const uint32_t vh_a = sb + SM_VH + ((16 * w + a_r) * 72 + a_c) * 2;
        const uint32_t vl_a = sb + SM_VL + ((16 * w + a_r) * 72 + a_c) * 2;
        const uint32_t uh_b = sb + SM_UH + (b_r * 72 + b_c) * 2;
        const uint32_t ul_b = sb + SM_UL + (b_r * 72 + b_c) * 2;

#pragma unroll
        for (int ks = 0; ks < 4; ks++) {
            uint32_t ah[4], al[4], bh[16], bl[16];
            LDSM4(ah[0], ah[1], ah[2], ah[3], vh_a + ks * 32);
            LDSM4(al[0], al[1], al[2], al[3], vl_a + ks * 32);
#pragma unroll
            for (int p = 0; p < 4; p++) {
                LDSM4(bh[4 * p], bh[4 * p + 1], bh[4 * p + 2], bh[4 * p + 3],
                      uh_b + p * 16 * 144 + ks * 32);
                LDSM4(bl[4 * p], bl[4 * p + 1], bl[4 * p + 2], bl[4 * p + 3],
                      ul_b + p * 16 * 144 + ks * 32);
            }
#pragma unroll
            for (int nb = 0; nb < 8; nb++) {
                int bi = (nb >> 1) * 4 + (nb & 1) * 2;
                MMA_BF16(c1[nb], ah[0], ah[1], ah[2], ah[3], bh[bi], bh[bi + 1]);
                MMA_BF16(c1[nb], ah[0], ah[1], ah[2], ah[3], bl[bi], bl[bi + 1]);
                MMA_BF16(c1[nb], al[0], al[1], al[2], al[3], bh[bi], bh[bi + 1]);
            }
        }

        // ---- epilogue: sigmoid + mask -> P^T [j][il] hi/lo ----
        {
            __nv_bfloat16* pth = (__nv_bfloat16*)(sm + SM_PTH);
            __nv_bfloat16* ptl = (__nv_bfloat16*)(sm + SM_PTL);
            int il0 = 16 * w + (lane >> 2);
#pragma unroll
            for (int nb = 0; nb < 8; nb++) {
#pragma unroll
                for (int q = 0; q < 4; q++) {
                    int il = il0 + ((q & 2) << 2);
                    int jl = 8 * nb + 2 * (lane & 3) + (q & 1);
                    float x = c1[nb][q] + bias;
                    float tv = __fdividef(1.f, 1.f + __expf(-x));
                    if (128 * t + il == 64 * jc + jl) tv = 0.f;
                    __nv_bfloat16 h, lo;
                    split2(tv, h, lo);
                    pth[jl * 136 + il] = h;
                    ptl[jl * 136 + il] = lo;
                }
            }
        }
        __syncthreads();

        // ---- GEMM2: D2[16j x 64dcat] per warp, K=128, 3-pass, accumulate ----
        const uint32_t pth_a = sb + SM_PTH + ((16 * mw + a_r) * 136 + a_c) * 2;
        const uint32_t ptl_a = sb + SM_PTL + ((16 * mw + a_r) * 136 + a_c) * 2;
        const uint32_t eh_b = sb + SM_EH + ((64 * nw + b_r) * 136 + b_c) * 2;
        const uint32_t el_b = sb + SM_EL + ((64 * nw + b_r) * 136 + b_c) * 2;

#pragma unroll
        for (int ks = 0; ks < 8; ks++) {
            uint32_t ah[4], al[4], bh[16], bl[16];
            LDSM4(ah[0], ah[1], ah[2], ah[3], pth_a + ks * 32);
            LDSM4(al[0], al[1], al[2], al[3], ptl_a + ks * 32);
#pragma unroll
            for (int p = 0; p < 4; p++) {
                LDSM4(bh[4 * p], bh[4 * p + 1], bh[4 * p + 2], bh[4 * p + 3],
                      eh_b + p * 16 * 272 + ks * 32);
                LDSM4(bl[4 * p], bl[4 * p + 1], bl[4 * p + 2], bl[4 * p + 3],
                      el_b + p * 16 * 272 + ks * 32);
            }
#pragma unroll
            for (int nb = 0; nb < 8; nb++) {
                int bi = (nb >> 1) * 4 + (nb & 1) * 2;
                MMA_BF16(d2[nb], ah[0], ah[1], ah[2], ah[3], bh[bi], bh[bi + 1]);
                MMA_BF16(d2[nb], ah[0], ah[1], ah[2], ah[3], bl[bi], bl[bi + 1]);
                MMA_BF16(d2[nb], al[0], al[1], al[2], al[3], bh[bi], bh[bi + 1]);
            }
        }
    }

    // ---- final: out = S + D2, direct coalesced-ish float2 stores ----
    {
        int jrow = 64 * jc + 16 * mw + (lane >> 2);
#pragma unroll
        for (int nb = 0; nb < 8; nb++) {
            int d = 8 * nb + 2 * (lane & 3);
            int b = nw;
#pragma unroll
            for (int half = 0; half < 2; half++) {
                int j = jrow + half * 8;
                long g = ((long)(b * NN + j)) * 64 + d;
                float2 sv = *(const float2*)(S + g);
                float2 ov;
                ov.x = sv.x + d2[nb][half * 2 + 0];
                ov.y = sv.y + d2[nb][half * 2 + 1];
                *(float2*)(out + g) = ov;
            }
        }
    }
}

extern "C" void kernel_launch(void* const* d_in, const int* in_sizes, int n_in,
                              void* d_out, int out_size) {
    const float* S    = (const float*)d_in[0];  // task_states   [2,8192,64]
    const float* prof = (const float*)d_in[1];  // proficiency   [2,8192]
    const float* U    = (const float*)d_in[2];  // task_embeddings [8192,64]
    const float* W    = (const float*)d_in[3];  // bilinear_weight [1,64,64]
    const float* bias = (const float*)d_in[4];  // bilinear_bias  [1]
    float* out = (float*)d_out;

    prep_embed<<<128, 256>>>(U, W);
    cudaFuncSetAttribute(prep_eff, cudaFuncAttributeMaxDynamicSharedMemorySize, 66048);
    prep_eff<<<64, 256, 66048>>>(S, prof);

    cudaFuncSetAttribute(dyadic_mma, cudaFuncAttributeMaxDynamicSharedMemorySize, SM_TOTAL);
    dyadic_mma<<<128, 256, SM_TOTAL>>>(S, bias, out);
}

// round 4
// speedup vs baseline: 3.9508x; 1.0994x over previous
#include <cuda_runtime.h>
#include <cuda_bf16.h>
#include <cstdint>

#define NN 8192
#define LEAK 0.7f

// ---------------- global scratch (row-major bf16 hi/lo splits) ------
__device__ __align__(16) __nv_bfloat16 gUh[NN * 64], gUl[NN * 64];     // U[row][k]
__device__ __align__(16) __nv_bfloat16 gVh[NN * 64], gVl[NN * 64];     // V[row][k]
__device__ __align__(16) __nv_bfloat16 gEh[128 * 128 * 64], gEl[128 * 128 * 64]; // [t][dcat][il]

// ---------------- helpers ----------------
__device__ __forceinline__ uint32_t smem_u32(const void* p) {
    uint32_t a;
    asm("{ .reg .u64 t; cvta.to.shared.u64 t, %1; cvt.u32.u64 %0, t; }" : "=r"(a) : "l"(p));
    return a;
}
#define LDSM4(R0, R1, R2, R3, A)                                                 \
    asm volatile("ldmatrix.sync.aligned.m8n8.x4.shared.b16 {%0,%1,%2,%3}, [%4];" \
                 : "=r"(R0), "=r"(R1), "=r"(R2), "=r"(R3) : "r"(A))
#define LDSM4T(R0, R1, R2, R3, A)                                                      \
    asm volatile("ldmatrix.sync.aligned.m8n8.x4.trans.shared.b16 {%0,%1,%2,%3}, [%4];" \
                 : "=r"(R0), "=r"(R1), "=r"(R2), "=r"(R3) : "r"(A))
#define MMA_BF16(c, a0, a1, a2, a3, b0, b1)                                   \
    asm volatile("mma.sync.aligned.m16n8k16.row.col.f32.bf16.bf16.f32 "       \
                 "{%0,%1,%2,%3},{%4,%5,%6,%7},{%8,%9},{%0,%1,%2,%3};"         \
                 : "+f"((c)[0]), "+f"((c)[1]), "+f"((c)[2]), "+f"((c)[3])     \
                 : "r"(a0), "r"(a1), "r"(a2), "r"(a3), "r"(b0), "r"(b1))
#define CP16(dst, src) \
    asm volatile("cp.async.cg.shared.global [%0], [%1], 16;" :: "r"(dst), "l"(src))
#define CP_COMMIT() asm volatile("cp.async.commit_group;" ::: "memory")
#define CP_WAIT1()  asm volatile("cp.async.wait_group 1;" ::: "memory")
#define CP_WAIT0()  asm volatile("cp.async.wait_group 0;" ::: "memory")

__device__ __forceinline__ void split2(float x, __nv_bfloat16& h, __nv_bfloat16& l) {
    h = __float2bfloat16(x);
    l = __float2bfloat16(x - __bfloat162float(h));
}

// ---------------- prep 1: V = U @ W; emit U,V hi/lo (grid 512) ----------------
__global__ void __launch_bounds__(256) prep_embed(const float* __restrict__ U,
                                                  const float* __restrict__ W) {
    __shared__ float Ws[64 * 64];
    int tid = threadIdx.x;
    for (int i = tid; i < 4096; i += 256) Ws[i] = W[i];
    __syncthreads();
    int w = tid >> 5, l = tid & 31;
#pragma unroll
    for (int r = 0; r < 2; r++) {
        int row = blockIdx.x * 16 + w * 2 + r;
        float u0 = U[row * 64 + l];
        float u1 = U[row * 64 + 32 + l];
        float v0 = 0.f, v1 = 0.f;
#pragma unroll
        for (int e = 0; e < 32; e++) {
            float ue = __shfl_sync(0xffffffffu, u0, e);
            v0 += ue * Ws[e * 64 + l];
            v1 += ue * Ws[e * 64 + 32 + l];
        }
#pragma unroll
        for (int e = 0; e < 32; e++) {
            float ue = __shfl_sync(0xffffffffu, u1, e);
            v0 += ue * Ws[(32 + e) * 64 + l];
            v1 += ue * Ws[(32 + e) * 64 + 32 + l];
        }
        __nv_bfloat16 h, lo;
        split2(u0, h, lo); gUh[row * 64 + l] = h;      gUl[row * 64 + l] = lo;
        split2(u1, h, lo); gUh[row * 64 + 32 + l] = h; gUl[row * 64 + 32 + l] = lo;
        split2(v0, h, lo); gVh[row * 64 + l] = h;      gVl[row * 64 + l] = lo;
        split2(v1, h, lo); gVh[row * 64 + 32 + l] = h; gVl[row * 64 + 32 + l] = lo;
    }
}

// ---------------- prep 2: eff[t][dcat][il] hi/lo, t = i-chunk of 64 ----------
__global__ void __launch_bounds__(256) prep_eff(const float* __restrict__ S,
                                                const float* __restrict__ prof) {
    __shared__ float es[64 * 129];
    __shared__ float gg[128];
    int t = blockIdx.x, tid = threadIdx.x;
    if (tid < 128) {
        int b = tid >> 6, il = tid & 63;
        float g = prof[b * NN + t * 64 + il] - LEAK;
        gg[tid] = g > 0.f ? g : 0.f;
    }
    __syncthreads();
    for (int idx = tid; idx < 8192; idx += 256) {
        int il = idx >> 7, dc = idx & 127;
        int b = dc >> 6, d = dc & 63;
        es[il * 129 + dc] = S[(b * NN + t * 64 + il) * 64 + d] * gg[b * 64 + il];
    }
    __syncthreads();
    int base = t * 8192;
    for (int idx = tid; idx < 8192; idx += 256) {
        int dc = idx >> 6, il = idx & 63;
        float x = es[il * 129 + dc];
        __nv_bfloat16 h, lo;
        split2(x, h, lo);
        gEh[base + dc * 64 + il] = h;
        gEl[base + dc * 64 + il] = lo;
    }
}

// ---------------- main fused, double-buffered mma.sync kernel ----------------
// smem byte offsets; rows padded to 144B (72 bf16)
#define SM_UH 0u
#define SM_UL 9216u
#define SM_STG 18432u        // stage s at SM_STG + s*55296: VH+0, VL+9216, EH+18432, EL+36864
#define STG_SZ 55296u
#define SM_PH 129024u        // P[il][j] rows, 144B stride
#define SM_PL 138240u
#define SM_TOTAL 147456u

__device__ __forceinline__ void stage_load(uint32_t stg, int t, int tid) {
#pragma unroll
    for (int idx = tid; idx < 1024; idx += 256) {
        int h = idx >> 9, rem = idx & 511, r = rem >> 3, c = rem & 7;
        uint32_t dst = stg + h * 9216u + r * 144u + c * 16u;
        const char* src = (const char*)(h ? gVl : gVh) + ((size_t)t * 4096 + r * 64 + c * 8) * 2;
        CP16(dst, src);
    }
#pragma unroll
    for (int idx = tid; idx < 2048; idx += 256) {
        int h = idx >> 10, rem = idx & 1023, r = rem >> 3, c = rem & 7;
        uint32_t dst = stg + 18432u + h * 18432u + r * 144u + c * 16u;
        const char* src = (const char*)(h ? gEl : gEh) + ((size_t)t * 8192 + r * 64 + c * 8) * 2;
        CP16(dst, src);
    }
}

__global__ void __launch_bounds__(256, 1) dyadic_mma(const float* __restrict__ S,
                                                     const float* __restrict__ bias_p,
                                                     float* __restrict__ out) {
    extern __shared__ char sm[];
    const uint32_t sb = smem_u32(sm);
    const int tid = threadIdx.x, w = tid >> 5, lane = tid & 31;
    const int jc = blockIdx.x;
    const float bias = bias_p[0];

    // resident U tile (64 rows x 64 k, hi/lo)
    {
        const uint4* sh = (const uint4*)gUh + jc * 512;
        const uint4* sl = (const uint4*)gUl + jc * 512;
        for (int idx = tid; idx < 512; idx += 256) {
            int r = idx >> 3, c = idx & 7;
            *(uint4*)(sm + SM_UH + r * 144 + c * 16) = sh[idx];
            *(uint4*)(sm + SM_UL + r * 144 + c * 16) = sl[idx];
        }
    }
    stage_load(sb + SM_STG, 0, tid);
    CP_COMMIT();

    // ldmatrix lane-address components
    const int a_r = lane & 15;                           // A rows (normal)
    const int a_c = (lane & 16) ? 8 : 0;                 // A col half
    const int b_r = (lane & 7) + ((lane & 16) ? 8 : 0);  // B rows
    const int b_c = (lane & 8) ? 8 : 0;                  // B col half
    const int t_r = (lane & 7) + ((lane & 16) ? 8 : 0);  // trans-A k row
    const int t_c = ((lane >> 3) & 1) ? 8 : 0;           // trans-A m col

    // GEMM1 partition: mi over i (4 x 16), nj over j (2 x 32)
    const int mi = w & 3, nj = w >> 2;
    // GEMM2 partition: mj over j (4 x 16), nd over dcat/batch (2 x 64)
    const int mj = w & 3, nd = w >> 2;

    float d2[8][4];
#pragma unroll
    for (int nb = 0; nb < 8; nb++)
#pragma unroll
        for (int q = 0; q < 4; q++) d2[nb][q] = 0.f;

    const uint32_t uh_b = sb + SM_UH + (32 * nj + b_r) * 144 + b_c * 2;
    const uint32_t ul_b = sb + SM_UL + (32 * nj + b_r) * 144 + b_c * 2;
    const uint32_t ph_a = sb + SM_PH + t_r * 144 + (16 * mj + t_c) * 2;
    const uint32_t pl_a = sb + SM_PL + t_r * 144 + (16 * mj + t_c) * 2;

    for (int t = 0; t < 128; t++) {
        const int s = t & 1;
        const uint32_t stg = sb + SM_STG + s * STG_SZ;

        if (t < 127) {
            stage_load(sb + SM_STG + (s ^ 1) * STG_SZ, t + 1, tid);
            CP_COMMIT();
            CP_WAIT1();
        } else {
            CP_WAIT0();
        }
        __syncthreads();

        // ---- GEMM1: C1[16i x 32j] per warp, K=64, 3-pass ----
        float c1[4][4];
#pragma unroll
        for (int nb = 0; nb < 4; nb++)
#pragma unroll
            for (int q = 0; q < 4; q++) c1[nb][q] = 0.f;

        const uint32_t vh_a = stg + (16 * mi + a_r) * 144 + a_c * 2;
        const uint32_t vl_a = stg + 9216u + (16 * mi + a_r) * 144 + a_c * 2;

#pragma unroll
        for (int ks = 0; ks < 4; ks++) {
            uint32_t ah[4], al[4], bh[8], bl[8];
            LDSM4(ah[0], ah[1], ah[2], ah[3], vh_a + ks * 32);
            LDSM4(al[0], al[1], al[2], al[3], vl_a + ks * 32);
#pragma unroll
            for (int p = 0; p < 2; p++) {
                LDSM4(bh[4 * p], bh[4 * p + 1], bh[4 * p + 2], bh[4 * p + 3],
                      uh_b + p * 16 * 144 + ks * 32);
                LDSM4(bl[4 * p], bl[4 * p + 1], bl[4 * p + 2], bl[4 * p + 3],
                      ul_b + p * 16 * 144 + ks * 32);
            }
#pragma unroll
            for (int nb = 0; nb < 4; nb++) {
                int bi = (nb >> 1) * 4 + (nb & 1) * 2;
                MMA_BF16(c1[nb], ah[0], ah[1], ah[2], ah[3], bh[bi], bh[bi + 1]);
                MMA_BF16(c1[nb], ah[0], ah[1], ah[2], ah[3], bl[bi], bl[bi + 1]);
                MMA_BF16(c1[nb], al[0], al[1], al[2], al[3], bh[bi], bh[bi + 1]);
            }
        }

        // ---- epilogue: sigmoid + mask -> P[il][j] hi/lo, packed bf16x2 stores ----
        {
#pragma unroll
            for (int half = 0; half < 2; half++) {
                int il = 16 * mi + (lane >> 2) + 8 * half;
                int gi = 64 * t + il;
                uint32_t rowh = sb + SM_PH + il * 144;
                uint32_t rowl = sb + SM_PL + il * 144;
#pragma unroll
                for (int nb = 0; nb < 4; nb++) {
                    int jl = 32 * nj + 8 * nb + 2 * (lane & 3);
                    float x0 = c1[nb][half * 2 + 0] + bias;
                    float x1 = c1[nb][half * 2 + 1] + bias;
                    float tv0 = __fdividef(1.f, 1.f + __expf(-x0));
                    float tv1 = __fdividef(1.f, 1.f + __expf(-x1));
                    if (gi == 64 * jc + jl) tv0 = 0.f;
                    if (gi == 64 * jc + jl + 1) tv1 = 0.f;
                    __nv_bfloat16 h0, l0, h1, l1;
                    split2(tv0, h0, l0);
                    split2(tv1, h1, l1);
                    uint32_t ph = (uint32_t)__bfloat16_as_ushort(h0) |
                                  ((uint32_t)__bfloat16_as_ushort(h1) << 16);
                    uint32_t pl = (uint32_t)__bfloat16_as_ushort(l0) |
                                  ((uint32_t)__bfloat16_as_ushort(l1) << 16);
                    asm volatile("st.shared.b32 [%0], %1;" :: "r"(rowh + jl * 2), "r"(ph));
                    asm volatile("st.shared.b32 [%0], %1;" :: "r"(rowl + jl * 2), "r"(pl));
                }
            }
        }
        __syncthreads();

        // ---- GEMM2: D2[16j x 64dcat] per warp, K=64, 3-pass, accumulate ----
        const uint32_t eh_b = stg + 18432u + (64 * nd + b_r) * 144 + b_c * 2;
        const uint32_t el_b = stg + 36864u + (64 * nd + b_r) * 144 + b_c * 2;

#pragma unroll
        for (int ks = 0; ks < 4; ks++) {
            uint32_t ah[4], al[4], bh[16], bl[16];
            LDSM4T(ah[0], ah[1], ah[2], ah[3], ph_a + ks * 16 * 144);
            LDSM4T(al[0], al[1], al[2], al[3], pl_a + ks * 16 * 144);
#pragma unroll
            for (int p = 0; p < 4; p++) {
                LDSM4(bh[4 * p], bh[4 * p + 1], bh[4 * p + 2], bh[4 * p + 3],
                      eh_b + p * 16 * 144 + ks * 32);
                LDSM4(bl[4 * p], bl[4 * p + 1], bl[4 * p + 2], bl[4 * p + 3],
                      el_b + p * 16 * 144 + ks * 32);
            }
#pragma unroll
            for (int nb = 0; nb < 8; nb++) {
                int bi = (nb >> 1) * 4 + (nb & 1) * 2;
                MMA_BF16(d2[nb], ah[0], ah[1], ah[2], ah[3], bh[bi], bh[bi + 1]);
                MMA_BF16(d2[nb], ah[0], ah[1], ah[2], ah[3], bl[bi], bl[bi + 1]);
                MMA_BF16(d2[nb], al[0], al[1], al[2], al[3], bh[bi], bh[bi + 1]);
            }
        }
        __syncthreads();
    }

    // ---- final: out = S + D2 ----
    {
        int jrow = 64 * jc + 16 * mj + (lane >> 2);
#pragma unroll
        for (int nb = 0; nb < 8; nb++) {
            int d = 8 * nb + 2 * (lane & 3);
#pragma unroll
            for (int half = 0; half < 2; half++) {
                int j = jrow + half * 8;
                size_t g = ((size_t)(nd * NN + j)) * 64 + d;
                float2 sv = *(const float2*)(S + g);
                float2 ov;
                ov.x = sv.x + d2[nb][half * 2 + 0];
                ov.y = sv.y + d2[nb][half * 2 + 1];
                *(float2*)(out + g) = ov;
            }
        }
    }
}

extern "C" void kernel_launch(void* const* d_in, const int* in_sizes, int n_in,
                              void* d_out, int out_size) {
    const float* S    = (const float*)d_in[0];  // task_states   [2,8192,64]
    const float* prof = (const float*)d_in[1];  // proficiency   [2,8192]
    const float* U    = (const float*)d_in[2];  // task_embeddings [8192,64]
    const float* W    = (const float*)d_in[3];  // bilinear_weight [1,64,64]
    const float* bias = (const float*)d_in[4];  // bilinear_bias  [1]
    float* out = (float*)d_out;

    prep_embed<<<512, 256>>>(U, W);
    prep_eff<<<128, 256>>>(S, prof);

    cudaFuncSetAttribute(dyadic_mma, cudaFuncAttributeMaxDynamicSharedMemorySize, SM_TOTAL);
    dyadic_mma<<<128, 256, SM_TOTAL>>>(S, bias, out);
}

// round 5
// speedup vs baseline: 4.1691x; 1.0553x over previous
#include <cuda_runtime.h>
#include <cuda_bf16.h>
#include <cstdint>

#define NN 8192
#define LEAK 0.7f

// ---------------- global scratch (row-major bf16 hi/lo splits) ------
__device__ __align__(16) __nv_bfloat16 gUh[NN * 64], gUl[NN * 64];     // U[row][k]
__device__ __align__(16) __nv_bfloat16 gVh[NN * 64], gVl[NN * 64];     // V[row][k]
__device__ __align__(16) __nv_bfloat16 gEh[128 * 128 * 64], gEl[128 * 128 * 64]; // [t][dcat][il]

// ---------------- helpers ----------------
__device__ __forceinline__ uint32_t smem_u32(const void* p) {
    uint32_t a;
    asm("{ .reg .u64 t; cvta.to.shared.u64 t, %1; cvt.u32.u64 %0, t; }" : "=r"(a) : "l"(p));
    return a;
}
#define LDSM4(R0, R1, R2, R3, A)                                                 \
    asm volatile("ldmatrix.sync.aligned.m8n8.x4.shared.b16 {%0,%1,%2,%3}, [%4];" \
                 : "=r"(R0), "=r"(R1), "=r"(R2), "=r"(R3) : "r"(A))
#define LDSM4T(R0, R1, R2, R3, A)                                                      \
    asm volatile("ldmatrix.sync.aligned.m8n8.x4.trans.shared.b16 {%0,%1,%2,%3}, [%4];" \
                 : "=r"(R0), "=r"(R1), "=r"(R2), "=r"(R3) : "r"(A))
#define MMA_BF16(c, a0, a1, a2, a3, b0, b1)                                   \
    asm volatile("mma.sync.aligned.m16n8k16.row.col.f32.bf16.bf16.f32 "       \
                 "{%0,%1,%2,%3},{%4,%5,%6,%7},{%8,%9},{%0,%1,%2,%3};"         \
                 : "+f"((c)[0]), "+f"((c)[1]), "+f"((c)[2]), "+f"((c)[3])     \
                 : "r"(a0), "r"(a1), "r"(a2), "r"(a3), "r"(b0), "r"(b1))
#define CP16(dst, src) \
    asm volatile("cp.async.cg.shared.global [%0], [%1], 16;" :: "r"(dst), "l"(src))
#define CP_COMMIT() asm volatile("cp.async.commit_group;" ::: "memory")
#define CP_WAIT0()  asm volatile("cp.async.wait_group 0;" ::: "memory")

__device__ __forceinline__ void split2(float x, __nv_bfloat16& h, __nv_bfloat16& l) {
    h = __float2bfloat16(x);
    l = __float2bfloat16(x - __bfloat162float(h));
}

// ---------------- prep 1: V = U @ W; one output per thread (grid 2048) -------
__global__ void __launch_bounds__(256) prep_embed(const float* __restrict__ U,
                                                  const float* __restrict__ W) {
    __shared__ float Ws[64 * 64];
    __shared__ float Ur[256];
    int tid = threadIdx.x;
    for (int i = tid; i < 4096; i += 256) Ws[i] = W[i];
    int r = tid >> 6, c = tid & 63;
    int row = blockIdx.x * 4 + r;
    Ur[tid] = U[row * 64 + c];
    __syncthreads();
    float acc = 0.f;
#pragma unroll 16
    for (int e = 0; e < 64; e++) acc += Ur[r * 64 + e] * Ws[e * 64 + c];
    __nv_bfloat16 h, lo;
    float u = Ur[tid];
    split2(u, h, lo);   gUh[row * 64 + c] = h; gUl[row * 64 + c] = lo;
    split2(acc, h, lo); gVh[row * 64 + c] = h; gVl[row * 64 + c] = lo;
}

// ---------------- prep 2: eff[t][dcat][il] hi/lo, t = i-chunk of 64 ----------
__global__ void __launch_bounds__(512) prep_eff(const float* __restrict__ S,
                                                const float* __restrict__ prof) {
    __shared__ float es[64 * 129];
    __shared__ float gg[128];
    int t = blockIdx.x, tid = threadIdx.x;
    if (tid < 128) {
        int b = tid >> 6, il = tid & 63;
        float g = prof[b * NN + t * 64 + il] - LEAK;
        gg[tid] = g > 0.f ? g : 0.f;
    }
    __syncthreads();
    for (int idx = tid; idx < 8192; idx += 512) {
        int il = idx >> 7, dc = idx & 127;
        int b = dc >> 6, d = dc & 63;
        es[il * 129 + dc] = S[(b * NN + t * 64 + il) * 64 + d] * gg[b * 64 + il];
    }
    __syncthreads();
    int base = t * 8192;
    for (int idx = tid; idx < 8192; idx += 512) {
        int dc = idx >> 6, il = idx & 63;
        float x = es[il * 129 + dc];
        __nv_bfloat16 h, lo;
        split2(x, h, lo);
        gEh[base + dc * 64 + il] = h;
        gEl[base + dc * 64 + il] = lo;
    }
}

// ---------------- main fused, double-buffered mma.sync kernel ----------------
// smem byte offsets; rows padded to 144B (72 bf16)
#define SM_UH 0u
#define SM_UL 9216u
#define SM_STG 18432u        // stage s at SM_STG + s*55296: VH+0, VL+9216, EH+18432, EL+36864
#define STG_SZ 55296u
#define SM_PH 129024u        // P[il][j] rows, 144B stride
#define SM_PL 138240u
#define SM_TOTAL 147456u

__device__ __forceinline__ void stage_load(uint32_t stg, int t, int tid) {
#pragma unroll
    for (int idx = tid; idx < 1024; idx += 256) {
        int h = idx >> 9, rem = idx & 511, r = rem >> 3, c = rem & 7;
        uint32_t dst = stg + h * 9216u + r * 144u + c * 16u;
        const char* src = (const char*)(h ? gVl : gVh) + ((size_t)t * 4096 + r * 64 + c * 8) * 2;
        CP16(dst, src);
    }
#pragma unroll
    for (int idx = tid; idx < 2048; idx += 256) {
        int h = idx >> 10, rem = idx & 1023, r = rem >> 3, c = rem & 7;
        uint32_t dst = stg + 18432u + h * 18432u + r * 144u + c * 16u;
        const char* src = (const char*)(h ? gEl : gEh) + ((size_t)t * 8192 + r * 64 + c * 8) * 2;
        CP16(dst, src);
    }
}

__global__ void __launch_bounds__(256, 1) dyadic_mma(const float* __restrict__ S,
                                                     const float* __restrict__ bias_p,
                                                     float* __restrict__ out) {
    extern __shared__ char sm[];
    const uint32_t sb = smem_u32(sm);
    const int tid = threadIdx.x, w = tid >> 5, lane = tid & 31;
    const int jc = blockIdx.x;
    const float bias = bias_p[0];

    // resident U tile (64 rows x 64 k, hi/lo) into smem, then hoist to registers
    {
        const uint4* sh = (const uint4*)gUh + jc * 512;
        const uint4* sl = (const uint4*)gUl + jc * 512;
        for (int idx = tid; idx < 512; idx += 256) {
            int r = idx >> 3, c = idx & 7;
            *(uint4*)(sm + SM_UH + r * 144 + c * 16) = sh[idx];
            *(uint4*)(sm + SM_UL + r * 144 + c * 16) = sl[idx];
        }
    }
    stage_load(sb + SM_STG, 0, tid);
    CP_COMMIT();

    // ldmatrix lane-address components
    const int a_r = lane & 15;                           // A rows (normal)
    const int a_c = (lane & 16) ? 8 : 0;                 // A col half
    const int b_r = (lane & 7) + ((lane & 16) ? 8 : 0);  // B rows
    const int b_c = (lane & 8) ? 8 : 0;                  // B col half
    const int t_r = (lane & 7) + ((lane & 16) ? 8 : 0);  // trans-A k row
    const int t_c = ((lane >> 3) & 1) ? 8 : 0;           // trans-A m col

    // GEMM1 partition: mi over i (4 x 16), nj over j (2 x 32)
    const int mi = w & 3, nj = w >> 2;
    // GEMM2 partition: mj over j (4 x 16), nd over dcat/batch (2 x 64)
    const int mj = w & 3, nd = w >> 2;

    float d2[8][4];
#pragma unroll
    for (int nb = 0; nb < 8; nb++)
#pragma unroll
        for (int q = 0; q < 4; q++) d2[nb][q] = 0.f;

    const uint32_t uh_b = sb + SM_UH + (32 * nj + b_r) * 144 + b_c * 2;
    const uint32_t ul_b = sb + SM_UL + (32 * nj + b_r) * 144 + b_c * 2;
    const uint32_t ph_a = sb + SM_PH + t_r * 144 + (16 * mj + t_c) * 2;
    const uint32_t pl_a = sb + SM_PL + t_r * 144 + (16 * mj + t_c) * 2;

    __syncthreads();  // U tile visible

    // hoist U fragments (loop-invariant GEMM1 B operand): [ks][p*4+r]
    uint32_t ubh[4][8], ubl[4][8];
#pragma unroll
    for (int ks = 0; ks < 4; ks++)
#pragma unroll
        for (int p = 0; p < 2; p++) {
            LDSM4(ubh[ks][4 * p], ubh[ks][4 * p + 1], ubh[ks][4 * p + 2], ubh[ks][4 * p + 3],
                  uh_b + p * 16 * 144 + ks * 32);
            LDSM4(ubl[ks][4 * p], ubl[ks][4 * p + 1], ubl[ks][4 * p + 2], ubl[ks][4 * p + 3],
                  ul_b + p * 16 * 144 + ks * 32);
        }

    for (int t = 0; t < 128; t++) {
        const int s = t & 1;
        const uint32_t stg = sb + SM_STG + s * STG_SZ;

        CP_WAIT0();
        __syncthreads();  // stage t visible; all warps past GEMM2(t-1) and its P reads

        if (t < 127) {
            stage_load(sb + SM_STG + (s ^ 1) * STG_SZ, t + 1, tid);
            CP_COMMIT();
        }

        // ---- GEMM1: C1[16i x 32j] per warp, K=64, 3-pass ----
        float c1[4][4];
#pragma unroll
        for (int nb = 0; nb < 4; nb++)
#pragma unroll
            for (int q = 0; q < 4; q++) c1[nb][q] = 0.f;

        const uint32_t vh_a = stg + (16 * mi + a_r) * 144 + a_c * 2;
        const uint32_t vl_a = stg + 9216u + (16 * mi + a_r) * 144 + a_c * 2;

#pragma unroll
        for (int ks = 0; ks < 4; ks++) {
            uint32_t ah[4], al[4];
            LDSM4(ah[0], ah[1], ah[2], ah[3], vh_a + ks * 32);
            LDSM4(al[0], al[1], al[2], al[3], vl_a + ks * 32);
#pragma unroll
            for (int nb = 0; nb < 4; nb++) {
                int bi = (nb >> 1) * 4 + (nb & 1) * 2;
                MMA_BF16(c1[nb], ah[0], ah[1], ah[2], ah[3], ubh[ks][bi], ubh[ks][bi + 1]);
                MMA_BF16(c1[nb], ah[0], ah[1], ah[2], ah[3], ubl[ks][bi], ubl[ks][bi + 1]);
                MMA_BF16(c1[nb], al[0], al[1], al[2], al[3], ubh[ks][bi], ubh[ks][bi + 1]);
            }
        }

        // ---- epilogue: sigmoid + mask -> P[il][j] hi/lo, packed bf16x2 stores ----
        {
#pragma unroll
            for (int half = 0; half < 2; half++) {
                int il = 16 * mi + (lane >> 2) + 8 * half;
                int gi = 64 * t + il;
                uint32_t rowh = sb + SM_PH + il * 144;
                uint32_t rowl = sb + SM_PL + il * 144;
#pragma unroll
                for (int nb = 0; nb < 4; nb++) {
                    int jl = 32 * nj + 8 * nb + 2 * (lane & 3);
                    float x0 = c1[nb][half * 2 + 0] + bias;
                    float x1 = c1[nb][half * 2 + 1] + bias;
                    float tv0 = __fdividef(1.f, 1.f + __expf(-x0));
                    float tv1 = __fdividef(1.f, 1.f + __expf(-x1));
                    if (gi == 64 * jc + jl) tv0 = 0.f;
                    if (gi == 64 * jc + jl + 1) tv1 = 0.f;
                    __nv_bfloat16 h0, l0, h1, l1;
                    split2(tv0, h0, l0);
                    split2(tv1, h1, l1);
                    uint32_t ph = (uint32_t)__bfloat16_as_ushort(h0) |
                                  ((uint32_t)__bfloat16_as_ushort(h1) << 16);
                    uint32_t pl = (uint32_t)__bfloat16_as_ushort(l0) |
                                  ((uint32_t)__bfloat16_as_ushort(l1) << 16);
                    asm volatile("st.shared.b32 [%0], %1;" :: "r"(rowh + jl * 2), "r"(ph));
                    asm volatile("st.shared.b32 [%0], %1;" :: "r"(rowl + jl * 2), "r"(pl));
                }
            }
        }
        __syncthreads();  // P visible

        // ---- GEMM2: D2[16j x 64dcat] per warp, K=64, 3-pass, accumulate ----
        const uint32_t eh_b = stg + 18432u + (64 * nd + b_r) * 144 + b_c * 2;
        const uint32_t el_b = stg + 36864u + (64 * nd + b_r) * 144 + b_c * 2;

#pragma unroll
        for (int ks = 0; ks < 4; ks++) {
            uint32_t ah[4], al[4], bh[16], bl[16];
            LDSM4T(ah[0], ah[1], ah[2], ah[3], ph_a + ks * 16 * 144);
            LDSM4T(al[0], al[1], al[2], al[3], pl_a + ks * 16 * 144);
#pragma unroll
            for (int p = 0; p < 4; p++) {
                LDSM4(bh[4 * p], bh[4 * p + 1], bh[4 * p + 2], bh[4 * p + 3],
                      eh_b + p * 16 * 144 + ks * 32);
                LDSM4(bl[4 * p], bl[4 * p + 1], bl[4 * p + 2], bl[4 * p + 3],
                      el_b + p * 16 * 144 + ks * 32);
            }
#pragma unroll
            for (int nb = 0; nb < 8; nb++) {
                int bi = (nb >> 1) * 4 + (nb & 1) * 2;
                MMA_BF16(d2[nb], ah[0], ah[1], ah[2], ah[3], bh[bi], bh[bi + 1]);
                MMA_BF16(d2[nb], ah[0], ah[1], ah[2], ah[3], bl[bi], bl[bi + 1]);
                MMA_BF16(d2[nb], al[0], al[1], al[2], al[3], bh[bi], bh[bi + 1]);
            }
        }
    }

    // ---- final: out = S + D2 ----
    {
        int jrow = 64 * jc + 16 * mj + (lane >> 2);
#pragma unroll
        for (int nb = 0; nb < 8; nb++) {
            int d = 8 * nb + 2 * (lane & 3);
#pragma unroll
            for (int half = 0; half < 2; half++) {
                int j = jrow + half * 8;
                size_t g = ((size_t)(nd * NN + j)) * 64 + d;
                float2 sv = *(const float2*)(S + g);
                float2 ov;
                ov.x = sv.x + d2[nb][half * 2 + 0];
                ov.y = sv.y + d2[nb][half * 2 + 1];
                *(float2*)(out + g) = ov;
            }
        }
    }
}

extern "C" void kernel_launch(void* const* d_in, const int* in_sizes, int n_in,
                              void* d_out, int out_size) {
    const float* S    = (const float*)d_in[0];  // task_states   [2,8192,64]
    const float* prof = (const float*)d_in[1];  // proficiency   [2,8192]
    const float* U    = (const float*)d_in[2];  // task_embeddings [8192,64]
    const float* W    = (const float*)d_in[3];  // bilinear_weight [1,64,64]
    const float* bias = (const float*)d_in[4];  // bilinear_bias  [1]
    float* out = (float*)d_out;

    prep_embed<<<2048, 256>>>(U, W);
    prep_eff<<<128, 512>>>(S, prof);

    cudaFuncSetAttribute(dyadic_mma, cudaFuncAttributeMaxDynamicSharedMemorySize, SM_TOTAL);
    dyadic_mma<<<128, 256, SM_TOTAL>>>(S, bias, out);
}